// round 3
// baseline (speedup 1.0000x reference)
#include <cuda_runtime.h>
#include <cstdint>
#include <math.h>

#define TT 512
#define NHEAD 8
#define DHEAD 64
#define DM 512

// ---------------- scratch (static device memory; no allocations) ----------------
__device__ float g_Q[64L*512*64];      // [bh][t][d]   8 MB
__device__ float g_K[64L*512*64];      // [bh][s][d]   8 MB
__device__ float g_V[64L*512*64];      // [bh][s][d]   8 MB
__device__ float g_S[64L*512*512];     // [bh][t][s]  64 MB (scores -> attn)
__device__ float g_C[8L*512*512];      // [b][t][dm]   8 MB

// ---------------- 128x128 tile, C = A * B^T core (BK=16, 8x8/thread) ----------------
__device__ __forceinline__ void gemm_abt_128(
    const float* __restrict__ A, const float* __restrict__ B,
    int Kdim, int lda, int ldb, float (&acc)[8][8])
{
    __shared__ float As[16][132];
    __shared__ float Bs[16][132];
    const int tid = threadIdx.x;
    const int ty = tid >> 4;
    const int tx = tid & 15;
    for (int k0 = 0; k0 < Kdim; k0 += 16) {
#pragma unroll
        for (int r = 0; r < 2; r++) {
            int f = tid + (r << 8);          // 0..511
            int row = f >> 2;                // 0..127
            int quad = (f & 3) << 2;         // 0,4,8,12
            float4 a4 = *(const float4*)(A + (size_t)row*lda + k0 + quad);
            As[quad+0][row] = a4.x; As[quad+1][row] = a4.y;
            As[quad+2][row] = a4.z; As[quad+3][row] = a4.w;
            float4 b4 = *(const float4*)(B + (size_t)row*ldb + k0 + quad);
            Bs[quad+0][row] = b4.x; Bs[quad+1][row] = b4.y;
            Bs[quad+2][row] = b4.z; Bs[quad+3][row] = b4.w;
        }
        __syncthreads();
#pragma unroll
        for (int k = 0; k < 16; k++) {
            float a[8], b[8];
            *(float4*)&a[0] = *(const float4*)&As[k][ty*8];
            *(float4*)&a[4] = *(const float4*)&As[k][ty*8+4];
            *(float4*)&b[0] = *(const float4*)&Bs[k][tx*8];
            *(float4*)&b[4] = *(const float4*)&Bs[k][tx*8+4];
#pragma unroll
            for (int i = 0; i < 8; i++)
#pragma unroll
                for (int j = 0; j < 8; j++)
                    acc[i][j] = fmaf(a[i], b[j], acc[i][j]);
        }
        __syncthreads();
    }
}

// ---------------- QKV projections: out[b,h,t,d] = x @ W^T + bias ----------------
__global__ __launch_bounds__(256,2) void proj_qkv_kernel(
    const float* __restrict__ x,
    const float* __restrict__ Wq, const float* __restrict__ bq,
    const float* __restrict__ Wk, const float* __restrict__ bk,
    const float* __restrict__ Wv, const float* __restrict__ bv)
{
    const int which = blockIdx.z;
    const float* W    = (which == 0) ? Wq : (which == 1) ? Wk : Wv;
    const float* bias = (which == 0) ? bq : (which == 1) ? bk : bv;
    float* out        = (which == 0) ? g_Q : (which == 1) ? g_K : g_V;

    const float* A  = x + (size_t)blockIdx.y * 128 * DM;
    const float* Bm = W + (size_t)blockIdx.x * 128 * DM;
    float acc[8][8] = {};
    gemm_abt_128(A, Bm, DM, DM, DM, acc);

    const int tid = threadIdx.x;
    const int ty = tid >> 4, tx = tid & 15;
#pragma unroll
    for (int i = 0; i < 8; i++) {
        int m = blockIdx.y*128 + ty*8 + i;      // b*T + t
        int b = m >> 9, t = m & 511;
#pragma unroll
        for (int jj = 0; jj < 8; jj += 4) {
            int n = blockIdx.x*128 + tx*8 + jj; // h*DH + d
            int h = n >> 6, d = n & 63;
            float4 bsv = *(const float4*)&bias[n];
            float4 v;
            v.x = acc[i][jj+0] + bsv.x;
            v.y = acc[i][jj+1] + bsv.y;
            v.z = acc[i][jj+2] + bsv.z;
            v.w = acc[i][jj+3] + bsv.w;
            *(float4*)&out[(((size_t)(b*NHEAD + h)*TT + t)*DHEAD) + d] = v;
        }
    }
}

// ---------------- content: S[bh,t,s] = Q[bh,t,:] . K[bh,s,:] (unscaled) ----------------
__global__ __launch_bounds__(256,2) void content_kernel()
{
    const int bh = blockIdx.z;
    const float* A  = g_Q + ((size_t)bh*TT + blockIdx.y*128) * DHEAD;
    const float* Bm = g_K + ((size_t)bh*TT + blockIdx.x*128) * DHEAD;
    float acc[8][8] = {};
    gemm_abt_128(A, Bm, DHEAD, DHEAD, DHEAD, acc);

    const int tid = threadIdx.x;
    const int ty = tid >> 4, tx = tid & 15;
#pragma unroll
    for (int i = 0; i < 8; i++) {
        int m = blockIdx.y*128 + ty*8 + i;
#pragma unroll
        for (int jj = 0; jj < 8; jj += 4) {
            int n = blockIdx.x*128 + tx*8 + jj;
            float4 v = { acc[i][jj+0], acc[i][jj+1], acc[i][jj+2], acc[i][jj+3] };
            *(float4*)&g_S[((size_t)bh*TT + m)*TT + n] = v;
        }
    }
}

// ----- position add + fused softmax: S = softmax((content + Q.rel^T)/8) -----
#define POS_CH 32
#define RSTR 548     // s-row stride in floats (8*68 + 4)
#define QSTR 68      // per-head segment stride
#define POS_SMEM ((2*POS_CH*RSTR + 64*QSTR)*4)

__device__ __forceinline__ void pos_load_chunk(const float* __restrict__ relt,
                                               int s0, float* dst, int tid)
{
    // 32 rows x 512 floats = 4096 float4, 16 per thread
#pragma unroll
    for (int r = 0; r < 16; r++) {
        int f = tid + (r << 8);
        int srow = f >> 7;            // 0..31
        int col = (f & 127) << 2;     // 0..508
        int hh = col >> 6;
        int dd = col & 63;
        const float* src = relt + (size_t)(s0 + srow)*DM + col;
        float* d = dst + srow*RSTR + hh*QSTR + dd;
        unsigned saddr = (unsigned)__cvta_generic_to_shared(d);
        asm volatile("cp.async.cg.shared.global [%0], [%1], 16;\n" :: "r"(saddr), "l"(src));
    }
}

__global__ __launch_bounds__(256,1) void pos_kernel(const float* __restrict__ rel)
{
    extern __shared__ float buf[];
    float* Rs0 = buf;
    float* Rs1 = buf + POS_CH*RSTR;
    float* Qs  = buf + 2*POS_CH*RSTR;

    const int t   = blockIdx.x;
    const int tid = threadIdx.x;

    // stage Q_t: 64 rows (bh) x 64 d
    for (int i = tid; i < 64*16; i += 256) {
        int bh = i >> 4;
        int d4 = (i & 15) << 2;
        *(float4*)&Qs[bh*QSTR + d4] =
            *(const float4*)&g_Q[((size_t)bh*TT + t)*DHEAD + d4];
    }

    const int sg = tid & 15;          // handles s_loc = sg and sg+16
    const int bg = (tid >> 4) & 1;    // b half: b = bg*4 .. bg*4+3
    const int h  = tid >> 5;          // head (constant per warp)
    const float* relt = rel + (size_t)t*TT*DM;

    pos_load_chunk(relt, 0, Rs0, tid);
    asm volatile("cp.async.commit_group;\n" ::: "memory");

    const int NCH = TT / POS_CH;   // 16
    for (int c = 0; c < NCH; c++) {
        float* cur = (c & 1) ? Rs1 : Rs0;
        float* nxt = (c & 1) ? Rs0 : Rs1;
        if (c + 1 < NCH) {
            pos_load_chunk(relt, (c+1)*POS_CH, nxt, tid);
            asm volatile("cp.async.commit_group;\n" ::: "memory");
            asm volatile("cp.async.wait_group 1;\n" ::: "memory");
        } else {
            asm volatile("cp.async.wait_group 0;\n" ::: "memory");
        }
        __syncthreads();

        float acc0[4] = {0.f,0.f,0.f,0.f};
        float acc1[4] = {0.f,0.f,0.f,0.f};
#pragma unroll
        for (int d4 = 0; d4 < DHEAD; d4 += 4) {
            float4 r0 = *(const float4*)&cur[(sg     )*RSTR + h*QSTR + d4];
            float4 r1 = *(const float4*)&cur[(sg + 16)*RSTR + h*QSTR + d4];
#pragma unroll
            for (int i = 0; i < 4; i++) {
                float4 q = *(const float4*)&Qs[(((bg<<2)+i)*8 + h)*QSTR + d4];
                acc0[i] += q.x*r0.x + q.y*r0.y + q.z*r0.z + q.w*r0.w;
                acc1[i] += q.x*r1.x + q.y*r1.y + q.z*r1.z + q.w*r1.w;
            }
        }
        const int sbase = c*POS_CH;
#pragma unroll
        for (int i = 0; i < 4; i++) {
            int bh = (((bg<<2)+i))*8 + h;
            size_t base = ((size_t)bh*TT + t)*TT + sbase;
            float o0 = g_S[base + sg];
            float o1 = g_S[base + sg + 16];
            g_S[base + sg]      = (o0 + acc0[i]) * 0.125f;
            g_S[base + sg + 16] = (o1 + acc1[i]) * 0.125f;
        }
        __syncthreads();
    }

    // ---- fused softmax tail: this CTA wrote ALL of S[bh, t, :] for bh=0..63.
    // __syncthreads above makes those global writes visible block-wide; rows
    // are 128 KB just written -> L2 resident. 8 warps x 8 rows each.
    const int warp = tid >> 5;
    const int lane = tid & 31;
#pragma unroll
    for (int rr = 0; rr < 8; rr++) {
        int bh = warp*8 + rr;
        float* p = g_S + ((size_t)bh*TT + t)*TT;

        float4 v[4];
        float mx = -1e30f;
#pragma unroll
        for (int i = 0; i < 4; i++) {
            v[i] = *(const float4*)&p[i*128 + lane*4];
            mx = fmaxf(mx, fmaxf(fmaxf(v[i].x, v[i].y), fmaxf(v[i].z, v[i].w)));
        }
#pragma unroll
        for (int o = 16; o > 0; o >>= 1)
            mx = fmaxf(mx, __shfl_xor_sync(0xffffffffu, mx, o));

        float sum = 0.f;
#pragma unroll
        for (int i = 0; i < 4; i++) {
            v[i].x = __expf(v[i].x - mx);
            v[i].y = __expf(v[i].y - mx);
            v[i].z = __expf(v[i].z - mx);
            v[i].w = __expf(v[i].w - mx);
            sum += v[i].x + v[i].y + v[i].z + v[i].w;
        }
#pragma unroll
        for (int o = 16; o > 0; o >>= 1)
            sum += __shfl_xor_sync(0xffffffffu, sum, o);

        const float inv = 1.0f / sum;
#pragma unroll
        for (int i = 0; i < 4; i++) {
            v[i].x *= inv; v[i].y *= inv; v[i].z *= inv; v[i].w *= inv;
            *(float4*)&p[i*128 + lane*4] = v[i];
        }
    }
}

// ---------------- context: C[b,t,h*64+d] = attn[bh] @ V[bh]  (128t x 64d tile) --------
__global__ __launch_bounds__(256,2) void context_kernel()
{
    const int bh = blockIdx.z;
    const int b = bh >> 3, h = bh & 7;
    const float* A  = g_S + (size_t)bh*TT*TT + (size_t)blockIdx.y*128*TT;
    const float* Vp = g_V + (size_t)bh*TT*DHEAD;

    __shared__ float As[32][132];
    __shared__ float Vs[32][68];
    const int tid = threadIdx.x;
    const int ty = tid >> 4, tx = tid & 15;
    float acc[8][4] = {};

    for (int k0 = 0; k0 < TT; k0 += 32) {
#pragma unroll
        for (int r = 0; r < 4; r++) {              // A: 128x32
            int f = tid + (r << 8);                // 0..1023
            int row = f >> 3;                      // 0..127
            int quad = (f & 7) << 2;               // 0..28
            float4 a4 = *(const float4*)(A + (size_t)row*TT + k0 + quad);
            As[quad+0][row] = a4.x; As[quad+1][row] = a4.y;
            As[quad+2][row] = a4.z; As[quad+3][row] = a4.w;
        }
#pragma unroll
        for (int r = 0; r < 2; r++) {              // V: 32x64
            int f = tid + (r << 8);                // 0..511
            int row = f >> 4;                      // 0..31
            int col = (f & 15) << 2;               // 0..60
            *(float4*)&Vs[row][col] = *(const float4*)(Vp + (size_t)(k0+row)*DHEAD + col);
        }
        __syncthreads();
#pragma unroll
        for (int k = 0; k < 32; k++) {
            float a[8];
            *(float4*)&a[0] = *(const float4*)&As[k][ty*8];
            *(float4*)&a[4] = *(const float4*)&As[k][ty*8+4];
            float4 bv4 = *(const float4*)&Vs[k][tx<<2];
            float bb[4] = { bv4.x, bv4.y, bv4.z, bv4.w };
#pragma unroll
            for (int i = 0; i < 8; i++)
#pragma unroll
                for (int j = 0; j < 4; j++)
                    acc[i][j] = fmaf(a[i], bb[j], acc[i][j]);
        }
        __syncthreads();
    }
#pragma unroll
    for (int i = 0; i < 8; i++) {
        int t = blockIdx.y*128 + ty*8 + i;
        float4 v = { acc[i][0], acc[i][1], acc[i][2], acc[i][3] };
        *(float4*)&g_C[((size_t)b*TT + t)*DM + h*DHEAD + (tx<<2)] = v;
    }
}

// ---------------- output projection: out = C @ Wo^T + bo ----------------
__global__ __launch_bounds__(256,2) void outproj_kernel(
    const float* __restrict__ Wo, const float* __restrict__ bo,
    float* __restrict__ out)
{
    const float* A  = g_C + (size_t)blockIdx.y * 128 * DM;
    const float* Bm = Wo  + (size_t)blockIdx.x * 128 * DM;
    float acc[8][8] = {};
    gemm_abt_128(A, Bm, DM, DM, DM, acc);

    const int tid = threadIdx.x;
    const int ty = tid >> 4, tx = tid & 15;
#pragma unroll
    for (int i = 0; i < 8; i++) {
        int m = blockIdx.y*128 + ty*8 + i;
#pragma unroll
        for (int jj = 0; jj < 8; jj += 4) {
            int n = blockIdx.x*128 + tx*8 + jj;
            float4 bsv = *(const float4*)&bo[n];
            float4 v;
            v.x = acc[i][jj+0] + bsv.x;
            v.y = acc[i][jj+1] + bsv.y;
            v.z = acc[i][jj+2] + bsv.z;
            v.w = acc[i][jj+3] + bsv.w;
            *(float4*)&out[(size_t)m*DM + n] = v;
        }
    }
}

extern "C" void kernel_launch(void* const* d_in, const int* in_sizes, int n_in,
                              void* d_out, int out_size)
{
    const float* x   = (const float*)d_in[0];
    const float* rel = (const float*)d_in[1];
    const float* Wq  = (const float*)d_in[2];
    const float* bq  = (const float*)d_in[3];
    const float* Wk  = (const float*)d_in[4];
    const float* bk  = (const float*)d_in[5];
    const float* Wv  = (const float*)d_in[6];
    const float* bv  = (const float*)d_in[7];
    const float* Wo  = (const float*)d_in[8];
    const float* bo  = (const float*)d_in[9];
    float* out = (float*)d_out;

    static int smem_set = 0;
    if (!smem_set) {
        cudaFuncSetAttribute(pos_kernel, cudaFuncAttributeMaxDynamicSharedMemorySize, POS_SMEM);
        smem_set = 1;
    }

    proj_qkv_kernel<<<dim3(4, 32, 3), 256>>>(x, Wq, bq, Wk, bk, Wv, bv);
    content_kernel<<<dim3(4, 4, 64), 256>>>();
    pos_kernel<<<512, 256, POS_SMEM>>>(rel);
    context_kernel<<<dim3(1, 4, 64), 256>>>();
    outproj_kernel<<<dim3(4, 32), 256>>>(Wo, bo, out);
}

// round 8
// speedup vs baseline: 1.1385x; 1.1385x over previous
#include <cuda_runtime.h>
#include <cstdint>
#include <math.h>

#define TT 512
#define NHEAD 8
#define DHEAD 64
#define DM 512

// ---------------- scratch (static device memory; no allocations) ----------------
__device__ float g_Q[64L*512*64];      // [bh][t][d]   8 MB
__device__ float g_K[64L*512*64];      // [bh][s][d]   8 MB
__device__ float g_V[64L*512*64];      // [bh][s][d]   8 MB
__device__ float g_S[64L*512*512];     // [bh][t][s]  64 MB (scores -> attn)
__device__ float g_C[8L*512*512];      // [b][t][dm]   8 MB

// ---------------- packed f32x2 helpers (Blackwell FFMA2) ----------------
__device__ __forceinline__ void ffma2(uint64_t& acc, uint64_t a2, uint64_t b2) {
    asm("fma.rn.f32x2 %0, %1, %2, %0;" : "+l"(acc) : "l"(a2), "l"(b2));
}
__device__ __forceinline__ uint64_t dup2(float a) {
    uint64_t r;
    asm("mov.b64 %0, {%1, %1};" : "=l"(r) : "f"(a));
    return r;
}
__device__ __forceinline__ float2 upk2(uint64_t v) {
    float2 f;
    asm("mov.b64 {%0, %1}, %2;" : "=f"(f.x), "=f"(f.y) : "l"(v));
    return f;
}

// ------- 128x128 tile, C = A * B^T core (BK=16, 8x8/thread, f32x2 FFMA,
//         register-prefetch software pipeline) -------
__device__ __forceinline__ void gemm_abt_128_f2(
    const float* __restrict__ A, const float* __restrict__ B,
    int Kdim, int lda, int ldb, uint64_t (&acc)[8][4])
{
    __shared__ float As[16][132];   // row stride 528 B (16B-aligned)
    __shared__ float Bs[16][132];
    const int tid = threadIdx.x;
    const int ty = tid >> 4;
    const int tx = tid & 15;

    // prologue: stage tile k0=0 in registers
    float4 a_reg[2], b_reg[2];
#pragma unroll
    for (int r = 0; r < 2; r++) {
        int f = tid + (r << 8);          // 0..511
        int row = f >> 2;                // 0..127
        int quad = (f & 3) << 2;         // 0,4,8,12
        a_reg[r] = *(const float4*)(A + (size_t)row*lda + quad);
        b_reg[r] = *(const float4*)(B + (size_t)row*ldb + quad);
    }

    for (int k0 = 0; k0 < Kdim; k0 += 16) {
        // store staged tile to smem (transpose)
#pragma unroll
        for (int r = 0; r < 2; r++) {
            int f = tid + (r << 8);
            int row = f >> 2;
            int quad = (f & 3) << 2;
            As[quad+0][row] = a_reg[r].x; As[quad+1][row] = a_reg[r].y;
            As[quad+2][row] = a_reg[r].z; As[quad+3][row] = a_reg[r].w;
            Bs[quad+0][row] = b_reg[r].x; Bs[quad+1][row] = b_reg[r].y;
            Bs[quad+2][row] = b_reg[r].z; Bs[quad+3][row] = b_reg[r].w;
        }
        __syncthreads();

        // prefetch next tile's global loads BEFORE compute (latency hidden)
        float4 a_nxt[2] = {}, b_nxt[2] = {};
        if (k0 + 16 < Kdim) {
#pragma unroll
            for (int r = 0; r < 2; r++) {
                int f = tid + (r << 8);
                int row = f >> 2;
                int quad = (f & 3) << 2;
                a_nxt[r] = *(const float4*)(A + (size_t)row*lda + k0 + 16 + quad);
                b_nxt[r] = *(const float4*)(B + (size_t)row*ldb + k0 + 16 + quad);
            }
        }

#pragma unroll
        for (int k = 0; k < 16; k++) {
            float a[8];
            *(float4*)&a[0] = *(const float4*)&As[k][ty*8];
            *(float4*)&a[4] = *(const float4*)&As[k][ty*8+4];
            // B pairs: 2x LDS.128 delivering 4 packed f32x2 operands
            ulonglong2 bp0 = *(const ulonglong2*)&Bs[k][tx*8];
            ulonglong2 bp1 = *(const ulonglong2*)&Bs[k][tx*8+4];
            uint64_t b2[4] = { bp0.x, bp0.y, bp1.x, bp1.y };
#pragma unroll
            for (int i = 0; i < 8; i++) {
                uint64_t a2 = dup2(a[i]);
#pragma unroll
                for (int j = 0; j < 4; j++)
                    ffma2(acc[i][j], a2, b2[j]);
            }
        }
        __syncthreads();
#pragma unroll
        for (int r = 0; r < 2; r++) { a_reg[r] = a_nxt[r]; b_reg[r] = b_nxt[r]; }
    }
}

// ---------------- QKV projections: out[b,h,t,d] = x @ W^T + bias ----------------
__global__ __launch_bounds__(256,2) void proj_qkv_kernel(
    const float* __restrict__ x,
    const float* __restrict__ Wq, const float* __restrict__ bq,
    const float* __restrict__ Wk, const float* __restrict__ bk,
    const float* __restrict__ Wv, const float* __restrict__ bv)
{
    const int which = blockIdx.z;
    const float* W    = (which == 0) ? Wq : (which == 1) ? Wk : Wv;
    const float* bias = (which == 0) ? bq : (which == 1) ? bk : bv;
    float* out        = (which == 0) ? g_Q : (which == 1) ? g_K : g_V;

    const float* A  = x + (size_t)blockIdx.y * 128 * DM;
    const float* Bm = W + (size_t)blockIdx.x * 128 * DM;
    uint64_t acc[8][4] = {};
    gemm_abt_128_f2(A, Bm, DM, DM, DM, acc);

    const int tid = threadIdx.x;
    const int ty = tid >> 4, tx = tid & 15;
#pragma unroll
    for (int i = 0; i < 8; i++) {
        int m = blockIdx.y*128 + ty*8 + i;      // b*T + t
        int b = m >> 9, t = m & 511;
#pragma unroll
        for (int jp = 0; jp < 4; jp += 2) {
            int n = blockIdx.x*128 + tx*8 + jp*2;  // h*DH + d
            int h = n >> 6, d = n & 63;
            float4 bsv = *(const float4*)&bias[n];
            float2 p0 = upk2(acc[i][jp]);
            float2 p1 = upk2(acc[i][jp+1]);
            float4 v;
            v.x = p0.x + bsv.x;
            v.y = p0.y + bsv.y;
            v.z = p1.x + bsv.z;
            v.w = p1.y + bsv.w;
            *(float4*)&out[(((size_t)(b*NHEAD + h)*TT + t)*DHEAD) + d] = v;
        }
    }
}

// ---------------- content: S[bh,t,s] = Q[bh,t,:] . K[bh,s,:] (unscaled) ----------------
__global__ __launch_bounds__(256,2) void content_kernel()
{
    const int bh = blockIdx.z;
    const float* A  = g_Q + ((size_t)bh*TT + blockIdx.y*128) * DHEAD;
    const float* Bm = g_K + ((size_t)bh*TT + blockIdx.x*128) * DHEAD;
    uint64_t acc[8][4] = {};
    gemm_abt_128_f2(A, Bm, DHEAD, DHEAD, DHEAD, acc);

    const int tid = threadIdx.x;
    const int ty = tid >> 4, tx = tid & 15;
#pragma unroll
    for (int i = 0; i < 8; i++) {
        int m = blockIdx.y*128 + ty*8 + i;
#pragma unroll
        for (int jp = 0; jp < 4; jp += 2) {
            int n = blockIdx.x*128 + tx*8 + jp*2;
            float2 p0 = upk2(acc[i][jp]);
            float2 p1 = upk2(acc[i][jp+1]);
            float4 v = { p0.x, p0.y, p1.x, p1.y };
            *(float4*)&g_S[((size_t)bh*TT + m)*TT + n] = v;
        }
    }
}

// ----- position add + fused softmax: S = softmax((content + Q.rel^T)/8) -----
// POS_CH=16 -> smem 87.6 KB -> 2 CTAs/SM: doubles in-flight cp.async per SM
// and covers barrier latency with the co-resident CTA.
#define POS_CH 16
#define RSTR 548     // s-row stride in floats (8*68 + 4)
#define QSTR 68      // per-head segment stride
#define POS_SMEM ((2*POS_CH*RSTR + 64*QSTR)*4)

__device__ __forceinline__ void pos_load_chunk(const float* __restrict__ relt,
                                               int s0, float* dst, int tid)
{
    // 16 rows x 512 floats = 2048 float4, 8 per thread
#pragma unroll
    for (int r = 0; r < 8; r++) {
        int f = tid + (r << 8);
        int srow = f >> 7;            // 0..15
        int col = (f & 127) << 2;     // 0..508
        int hh = col >> 6;
        int dd = col & 63;
        const float* src = relt + (size_t)(s0 + srow)*DM + col;
        float* d = dst + srow*RSTR + hh*QSTR + dd;
        unsigned saddr = (unsigned)__cvta_generic_to_shared(d);
        asm volatile("cp.async.cg.shared.global [%0], [%1], 16;\n" :: "r"(saddr), "l"(src));
    }
}

__global__ __launch_bounds__(256,2) void pos_kernel(const float* __restrict__ rel)
{
    extern __shared__ float buf[];
    float* Rs0 = buf;
    float* Rs1 = buf + POS_CH*RSTR;
    float* Qs  = buf + 2*POS_CH*RSTR;

    const int t   = blockIdx.x;
    const int tid = threadIdx.x;

    // stage Q_t: 64 rows (bh) x 64 d  (visible after first in-loop barrier)
    for (int i = tid; i < 64*16; i += 256) {
        int bh = i >> 4;
        int d4 = (i & 15) << 2;
        *(float4*)&Qs[bh*QSTR + d4] =
            *(const float4*)&g_Q[((size_t)bh*TT + t)*DHEAD + d4];
    }

    const int sg = tid & 15;          // s within chunk
    const int bg = (tid >> 4) & 1;    // b half: b = bg*4 .. bg*4+3
    const int h  = tid >> 5;          // head (constant per warp)
    const float* relt = rel + (size_t)t*TT*DM;

    pos_load_chunk(relt, 0, Rs0, tid);
    asm volatile("cp.async.commit_group;\n" ::: "memory");

    const int NCH = TT / POS_CH;   // 32
    for (int c = 0; c < NCH; c++) {
        float* cur = (c & 1) ? Rs1 : Rs0;
        float* nxt = (c & 1) ? Rs0 : Rs1;
        if (c + 1 < NCH) {
            pos_load_chunk(relt, (c+1)*POS_CH, nxt, tid);
            asm volatile("cp.async.commit_group;\n" ::: "memory");
            asm volatile("cp.async.wait_group 1;\n" ::: "memory");
        } else {
            asm volatile("cp.async.wait_group 0;\n" ::: "memory");
        }
        __syncthreads();

        // packed f32x2 dot products over the d dimension
        uint64_t acc0[4] = {0ull,0ull,0ull,0ull};
#pragma unroll
        for (int d4 = 0; d4 < DHEAD; d4 += 4) {
            ulonglong2 r0 = *(const ulonglong2*)&cur[sg*RSTR + h*QSTR + d4];
#pragma unroll
            for (int i = 0; i < 4; i++) {
                ulonglong2 q = *(const ulonglong2*)&Qs[(((bg<<2)+i)*8 + h)*QSTR + d4];
                ffma2(acc0[i], q.x, r0.x);
                ffma2(acc0[i], q.y, r0.y);
            }
        }
        const int sbase = c*POS_CH;
#pragma unroll
        for (int i = 0; i < 4; i++) {
            int bh = (((bg<<2)+i))*8 + h;
            size_t base = ((size_t)bh*TT + t)*TT + sbase;
            float2 a0 = upk2(acc0[i]);
            float o0 = g_S[base + sg];
            g_S[base + sg] = (o0 + a0.x + a0.y) * 0.125f;
        }
        __syncthreads();
    }

    // ---- fused softmax tail: this CTA wrote ALL of S[bh, t, :] for bh=0..63.
    const int warp = tid >> 5;
    const int lane = tid & 31;
#pragma unroll
    for (int rr = 0; rr < 8; rr++) {
        int bh = warp*8 + rr;
        float* p = g_S + ((size_t)bh*TT + t)*TT;

        float4 v[4];
        float mx = -1e30f;
#pragma unroll
        for (int i = 0; i < 4; i++) {
            v[i] = *(const float4*)&p[i*128 + lane*4];
            mx = fmaxf(mx, fmaxf(fmaxf(v[i].x, v[i].y), fmaxf(v[i].z, v[i].w)));
        }
#pragma unroll
        for (int o = 16; o > 0; o >>= 1)
            mx = fmaxf(mx, __shfl_xor_sync(0xffffffffu, mx, o));

        float sum = 0.f;
#pragma unroll
        for (int i = 0; i < 4; i++) {
            v[i].x = __expf(v[i].x - mx);
            v[i].y = __expf(v[i].y - mx);
            v[i].z = __expf(v[i].z - mx);
            v[i].w = __expf(v[i].w - mx);
            sum += v[i].x + v[i].y + v[i].z + v[i].w;
        }
#pragma unroll
        for (int o = 16; o > 0; o >>= 1)
            sum += __shfl_xor_sync(0xffffffffu, sum, o);

        const float inv = 1.0f / sum;
#pragma unroll
        for (int i = 0; i < 4; i++) {
            v[i].x *= inv; v[i].y *= inv; v[i].z *= inv; v[i].w *= inv;
            *(float4*)&p[i*128 + lane*4] = v[i];
        }
    }
}

// ---------------- context: C[b,t,h*64+d] = attn[bh] @ V[bh]  (128t x 64d tile,
//                  register-prefetch pipeline) --------
__global__ __launch_bounds__(256,2) void context_kernel()
{
    const int bh = blockIdx.z;
    const int b = bh >> 3, h = bh & 7;
    const float* A  = g_S + (size_t)bh*TT*TT + (size_t)blockIdx.y*128*TT;
    const float* Vp = g_V + (size_t)bh*TT*DHEAD;

    __shared__ float As[32][132];
    __shared__ float Vs[32][68];    // row stride 272 B (16B-aligned)
    const int tid = threadIdx.x;
    const int ty = tid >> 4, tx = tid & 15;
    uint64_t acc[8][2] = {};

    // prologue: stage k0=0 tiles in registers
    float4 a_reg[4], v_reg[2];
#pragma unroll
    for (int r = 0; r < 4; r++) {
        int f = tid + (r << 8);
        int row = f >> 3;
        int quad = (f & 7) << 2;
        a_reg[r] = *(const float4*)(A + (size_t)row*TT + quad);
    }
#pragma unroll
    for (int r = 0; r < 2; r++) {
        int f = tid + (r << 8);
        int row = f >> 4;
        int col = (f & 15) << 2;
        v_reg[r] = *(const float4*)(Vp + (size_t)row*DHEAD + col);
    }

    for (int k0 = 0; k0 < TT; k0 += 32) {
#pragma unroll
        for (int r = 0; r < 4; r++) {              // A: 128x32 (transpose store)
            int f = tid + (r << 8);
            int row = f >> 3;
            int quad = (f & 7) << 2;
            As[quad+0][row] = a_reg[r].x; As[quad+1][row] = a_reg[r].y;
            As[quad+2][row] = a_reg[r].z; As[quad+3][row] = a_reg[r].w;
        }
#pragma unroll
        for (int r = 0; r < 2; r++) {              // V: 32x64
            int f = tid + (r << 8);
            int row = f >> 4;
            int col = (f & 15) << 2;
            *(float4*)&Vs[row][col] = v_reg[r];
        }
        __syncthreads();

        float4 a_nxt[4] = {}, v_nxt[2] = {};
        if (k0 + 32 < TT) {
#pragma unroll
            for (int r = 0; r < 4; r++) {
                int f = tid + (r << 8);
                int row = f >> 3;
                int quad = (f & 7) << 2;
                a_nxt[r] = *(const float4*)(A + (size_t)row*TT + k0 + 32 + quad);
            }
#pragma unroll
            for (int r = 0; r < 2; r++) {
                int f = tid + (r << 8);
                int row = f >> 4;
                int col = (f & 15) << 2;
                v_nxt[r] = *(const float4*)(Vp + (size_t)(k0 + 32 + row)*DHEAD + col);
            }
        }

#pragma unroll
        for (int k = 0; k < 32; k++) {
            float a[8];
            *(float4*)&a[0] = *(const float4*)&As[k][ty*8];
            *(float4*)&a[4] = *(const float4*)&As[k][ty*8+4];
            ulonglong2 bp = *(const ulonglong2*)&Vs[k][tx<<2];
            uint64_t b2[2] = { bp.x, bp.y };
#pragma unroll
            for (int i = 0; i < 8; i++) {
                uint64_t a2 = dup2(a[i]);
                ffma2(acc[i][0], a2, b2[0]);
                ffma2(acc[i][1], a2, b2[1]);
            }
        }
        __syncthreads();
#pragma unroll
        for (int r = 0; r < 4; r++) a_reg[r] = a_nxt[r];
#pragma unroll
        for (int r = 0; r < 2; r++) v_reg[r] = v_nxt[r];
    }
#pragma unroll
    for (int i = 0; i < 8; i++) {
        int t = blockIdx.y*128 + ty*8 + i;
        float2 p0 = upk2(acc[i][0]);
        float2 p1 = upk2(acc[i][1]);
        float4 v = { p0.x, p0.y, p1.x, p1.y };
        *(float4*)&g_C[((size_t)b*TT + t)*DM + h*DHEAD + (tx<<2)] = v;
    }
}

// ---------------- output projection: out = C @ Wo^T + bo ----------------
__global__ __launch_bounds__(256,2) void outproj_kernel(
    const float* __restrict__ Wo, const float* __restrict__ bo,
    float* __restrict__ out)
{
    const float* A  = g_C + (size_t)blockIdx.y * 128 * DM;
    const float* Bm = Wo  + (size_t)blockIdx.x * 128 * DM;
    uint64_t acc[8][4] = {};
    gemm_abt_128_f2(A, Bm, DM, DM, DM, acc);

    const int tid = threadIdx.x;
    const int ty = tid >> 4, tx = tid & 15;
#pragma unroll
    for (int i = 0; i < 8; i++) {
        int m = blockIdx.y*128 + ty*8 + i;
#pragma unroll
        for (int jp = 0; jp < 4; jp += 2) {
            int n = blockIdx.x*128 + tx*8 + jp*2;
            float4 bsv = *(const float4*)&bo[n];
            float2 p0 = upk2(acc[i][jp]);
            float2 p1 = upk2(acc[i][jp+1]);
            float4 v;
            v.x = p0.x + bsv.x;
            v.y = p0.y + bsv.y;
            v.z = p1.x + bsv.z;
            v.w = p1.y + bsv.w;
            *(float4*)&out[(size_t)m*DM + n] = v;
        }
    }
}

extern "C" void kernel_launch(void* const* d_in, const int* in_sizes, int n_in,
                              void* d_out, int out_size)
{
    const float* x   = (const float*)d_in[0];
    const float* rel = (const float*)d_in[1];
    const float* Wq  = (const float*)d_in[2];
    const float* bq  = (const float*)d_in[3];
    const float* Wk  = (const float*)d_in[4];
    const float* bk  = (const float*)d_in[5];
    const float* Wv  = (const float*)d_in[6];
    const float* bv  = (const float*)d_in[7];
    const float* Wo  = (const float*)d_in[8];
    const float* bo  = (const float*)d_in[9];
    float* out = (float*)d_out;

    cudaFuncSetAttribute(pos_kernel, cudaFuncAttributeMaxDynamicSharedMemorySize, POS_SMEM);

    proj_qkv_kernel<<<dim3(4, 32, 3), 256>>>(x, Wq, bq, Wk, bk, Wv, bv);
    content_kernel<<<dim3(4, 4, 64), 256>>>();
    pos_kernel<<<512, 256, POS_SMEM>>>(rel);
    context_kernel<<<dim3(1, 4, 64), 256>>>();
    outproj_kernel<<<dim3(4, 32), 256>>>(Wo, bo, out);
}

// round 17
// speedup vs baseline: 1.1868x; 1.0425x over previous
#include <cuda_runtime.h>
#include <cstdint>
#include <math.h>

#define TT 512
#define NHEAD 8
#define DHEAD 64
#define DM 512

// ---------------- scratch (static device memory; no allocations) ----------------
__device__ float g_Q[64L*512*64];      // [bh][t][d]   8 MB
__device__ float g_K[64L*512*64];      // [bh][s][d]   8 MB
__device__ float g_V[64L*512*64];      // [bh][s][d]   8 MB
__device__ float g_S[64L*512*512];     // [bh][t][s]  64 MB (scores -> attn)
__device__ float g_C[8L*512*512];      // [b][t][dm]   8 MB

// ---------------- packed f32x2 helpers (Blackwell FFMA2) ----------------
__device__ __forceinline__ void ffma2(uint64_t& acc, uint64_t a2, uint64_t b2) {
    asm("fma.rn.f32x2 %0, %1, %2, %0;" : "+l"(acc) : "l"(a2), "l"(b2));
}
__device__ __forceinline__ uint64_t dup2(float a) {
    uint64_t r;
    asm("mov.b64 %0, {%1, %1};" : "=l"(r) : "f"(a));
    return r;
}
__device__ __forceinline__ float2 upk2(uint64_t v) {
    float2 f;
    asm("mov.b64 {%0, %1}, %2;" : "=f"(f.x), "=f"(f.y) : "l"(v));
    return f;
}

// ---------------- tf32 helpers ----------------
__device__ __forceinline__ float tf32r(float x) {
    uint32_t u;
    asm("cvt.rna.tf32.f32 %0, %1;" : "=r"(u) : "f"(x));
    return __uint_as_float(u);
}
__device__ __forceinline__ void mma_tf32(float (&d)[4],
    uint32_t a0, uint32_t a1, uint32_t a2, uint32_t a3,
    uint32_t b0, uint32_t b1)
{
    asm("mma.sync.aligned.m16n8k8.row.col.f32.tf32.tf32.f32 "
        "{%0,%1,%2,%3}, {%4,%5,%6,%7}, {%8,%9}, {%0,%1,%2,%3};"
        : "+f"(d[0]), "+f"(d[1]), "+f"(d[2]), "+f"(d[3])
        : "r"(a0), "r"(a1), "r"(a2), "r"(a3), "r"(b0), "r"(b1));
}
__device__ __forceinline__ uint32_t fbits(float x) { return __float_as_uint(x); }

// ------- 128x128 tile, C = A * B^T core, 3xTF32 mma.sync (fp32 accuracy) -------
// 8 warps: warp tile 64x32 (wm = wid>>2 in {0,1}, wn = wid&3 in {0..3}).
// smem stride 136 -> conflict-free fragment loads (bank = 8*(lane%4)+(lane>>2)+c).
#define AST 136

__device__ __forceinline__ void gemm_abt_tf32(
    const float* __restrict__ A, const float* __restrict__ B,
    int Kdim, int lda, int ldb, float (&acc)[4][4][4])
{
    __shared__ float Ah[16*AST], Al[16*AST], Bh[16*AST], Bl[16*AST];
    const int tid  = threadIdx.x;
    const int lane = tid & 31;
    const int wid  = tid >> 5;
    const int m0 = (wid >> 2) * 64;
    const int n0 = (wid & 3) * 32;
    const int r4 = lane & 3;
    const int q8 = lane >> 2;

    // prologue: stage tile k0=0 in registers
    float4 a_reg[2], b_reg[2];
#pragma unroll
    for (int r = 0; r < 2; r++) {
        int f = tid + (r << 8);          // 0..511
        int row = f >> 2;                // 0..127
        int quad = (f & 3) << 2;         // 0,4,8,12
        a_reg[r] = *(const float4*)(A + (size_t)row*lda + quad);
        b_reg[r] = *(const float4*)(B + (size_t)row*ldb + quad);
    }

    for (int k0 = 0; k0 < Kdim; k0 += 16) {
        // split to tf32 hi/lo and store transposed: [k][m] / [k][n]
#pragma unroll
        for (int r = 0; r < 2; r++) {
            int f = tid + (r << 8);
            int row = f >> 2;
            int quad = (f & 3) << 2;
            float av[4] = { a_reg[r].x, a_reg[r].y, a_reg[r].z, a_reg[r].w };
            float bv[4] = { b_reg[r].x, b_reg[r].y, b_reg[r].z, b_reg[r].w };
#pragma unroll
            for (int i = 0; i < 4; i++) {
                float ahi = tf32r(av[i]);
                float alo = tf32r(av[i] - ahi);
                Ah[(quad+i)*AST + row] = ahi;
                Al[(quad+i)*AST + row] = alo;
                float bhi = tf32r(bv[i]);
                float blo = tf32r(bv[i] - bhi);
                Bh[(quad+i)*AST + row] = bhi;
                Bl[(quad+i)*AST + row] = blo;
            }
        }
        __syncthreads();

        // prefetch next tile's global loads BEFORE compute
        float4 a_nxt[2] = {}, b_nxt[2] = {};
        if (k0 + 16 < Kdim) {
#pragma unroll
            for (int r = 0; r < 2; r++) {
                int f = tid + (r << 8);
                int row = f >> 2;
                int quad = (f & 3) << 2;
                a_nxt[r] = *(const float4*)(A + (size_t)row*lda + k0 + 16 + quad);
                b_nxt[r] = *(const float4*)(B + (size_t)row*ldb + k0 + 16 + quad);
            }
        }

#pragma unroll
        for (int ks = 0; ks < 16; ks += 8) {
            // B fragments for 4 n-tiles
            uint32_t bhf[4][2], blf[4][2];
#pragma unroll
            for (int nt = 0; nt < 4; nt++) {
                int c = n0 + nt*8 + q8;
                bhf[nt][0] = fbits(Bh[(ks+r4  )*AST + c]);
                bhf[nt][1] = fbits(Bh[(ks+r4+4)*AST + c]);
                blf[nt][0] = fbits(Bl[(ks+r4  )*AST + c]);
                blf[nt][1] = fbits(Bl[(ks+r4+4)*AST + c]);
            }
#pragma unroll
            for (int mt = 0; mt < 4; mt++) {
                int mr = m0 + mt*16 + q8;
                uint32_t ah[4], al[4];
                ah[0] = fbits(Ah[(ks+r4  )*AST + mr]);
                ah[1] = fbits(Ah[(ks+r4  )*AST + mr + 8]);
                ah[2] = fbits(Ah[(ks+r4+4)*AST + mr]);
                ah[3] = fbits(Ah[(ks+r4+4)*AST + mr + 8]);
                al[0] = fbits(Al[(ks+r4  )*AST + mr]);
                al[1] = fbits(Al[(ks+r4  )*AST + mr + 8]);
                al[2] = fbits(Al[(ks+r4+4)*AST + mr]);
                al[3] = fbits(Al[(ks+r4+4)*AST + mr + 8]);
#pragma unroll
                for (int nt = 0; nt < 4; nt++) {
                    mma_tf32(acc[mt][nt], al[0],al[1],al[2],al[3], bhf[nt][0],bhf[nt][1]);
                    mma_tf32(acc[mt][nt], ah[0],ah[1],ah[2],ah[3], blf[nt][0],blf[nt][1]);
                    mma_tf32(acc[mt][nt], ah[0],ah[1],ah[2],ah[3], bhf[nt][0],bhf[nt][1]);
                }
            }
        }
        __syncthreads();
#pragma unroll
        for (int r = 0; r < 2; r++) { a_reg[r] = a_nxt[r]; b_reg[r] = b_nxt[r]; }
    }
}

// ---------------- QKV projections: out[b,h,t,d] = x @ W^T + bias ----------------
__global__ __launch_bounds__(256,2) void proj_qkv_kernel(
    const float* __restrict__ x,
    const float* __restrict__ Wq, const float* __restrict__ bq,
    const float* __restrict__ Wk, const float* __restrict__ bk,
    const float* __restrict__ Wv, const float* __restrict__ bv)
{
    const int which = blockIdx.z;
    const float* W    = (which == 0) ? Wq : (which == 1) ? Wk : Wv;
    const float* bias = (which == 0) ? bq : (which == 1) ? bk : bv;
    float* out        = (which == 0) ? g_Q : (which == 1) ? g_K : g_V;

    const float* A  = x + (size_t)blockIdx.y * 128 * DM;
    const float* Bm = W + (size_t)blockIdx.x * 128 * DM;
    float acc[4][4][4] = {};
    gemm_abt_tf32(A, Bm, DM, DM, DM, acc);

    const int tid = threadIdx.x;
    const int lane = tid & 31;
    const int wid = tid >> 5;
    const int m0 = (wid >> 2) * 64;
    const int n0 = (wid & 3) * 32;
    const int r4 = lane & 3, q8 = lane >> 2;
#pragma unroll
    for (int mt = 0; mt < 4; mt++) {
#pragma unroll
        for (int nt = 0; nt < 4; nt++) {
            int ncol = n0 + nt*8 + 2*r4;
            int n = blockIdx.x*128 + ncol;       // h*DH + d (pair stays in head)
            int h = n >> 6, d = n & 63;
            float2 bias2 = *(const float2*)&bias[n];
#pragma unroll
            for (int hf = 0; hf < 2; hf++) {
                int row = m0 + mt*16 + q8 + hf*8;
                int m = blockIdx.y*128 + row;    // b*T + t
                int b = m >> 9, t = m & 511;
                float2 v = { acc[mt][nt][hf*2+0] + bias2.x,
                             acc[mt][nt][hf*2+1] + bias2.y };
                *(float2*)&out[(((size_t)(b*NHEAD + h)*TT + t)*DHEAD) + d] = v;
            }
        }
    }
}

// ---------------- content: S[bh,t,s] = Q[bh,t,:] . K[bh,s,:] (unscaled) ----------------
__global__ __launch_bounds__(256,2) void content_kernel()
{
    const int bh = blockIdx.z;
    const float* A  = g_Q + ((size_t)bh*TT + blockIdx.y*128) * DHEAD;
    const float* Bm = g_K + ((size_t)bh*TT + blockIdx.x*128) * DHEAD;
    float acc[4][4][4] = {};
    gemm_abt_tf32(A, Bm, DHEAD, DHEAD, DHEAD, acc);

    const int tid = threadIdx.x;
    const int lane = tid & 31;
    const int wid = tid >> 5;
    const int m0 = (wid >> 2) * 64;
    const int n0 = (wid & 3) * 32;
    const int r4 = lane & 3, q8 = lane >> 2;
#pragma unroll
    for (int mt = 0; mt < 4; mt++) {
#pragma unroll
        for (int nt = 0; nt < 4; nt++) {
            int n = blockIdx.x*128 + n0 + nt*8 + 2*r4;
#pragma unroll
            for (int hf = 0; hf < 2; hf++) {
                int m = blockIdx.y*128 + m0 + mt*16 + q8 + hf*8;
                float2 v = { acc[mt][nt][hf*2+0], acc[mt][nt][hf*2+1] };
                *(float2*)&g_S[((size_t)bh*TT + m)*TT + n] = v;
            }
        }
    }
}

// ----- position add + fused softmax: S = softmax((content + Q.rel^T)/8) -----
// POS_CH=16 -> smem 87.6 KB -> 2 CTAs/SM.
#define POS_CH 16
#define RSTR 548     // s-row stride in floats (8*68 + 4)
#define QSTR 68      // per-head segment stride
#define POS_SMEM ((2*POS_CH*RSTR + 64*QSTR)*4)

__device__ __forceinline__ void pos_load_chunk(const float* __restrict__ relt,
                                               int s0, float* dst, int tid)
{
#pragma unroll
    for (int r = 0; r < 8; r++) {
        int f = tid + (r << 8);
        int srow = f >> 7;            // 0..15
        int col = (f & 127) << 2;     // 0..508
        int hh = col >> 6;
        int dd = col & 63;
        const float* src = relt + (size_t)(s0 + srow)*DM + col;
        float* d = dst + srow*RSTR + hh*QSTR + dd;
        unsigned saddr = (unsigned)__cvta_generic_to_shared(d);
        asm volatile("cp.async.cg.shared.global [%0], [%1], 16;\n" :: "r"(saddr), "l"(src));
    }
}

__global__ __launch_bounds__(256,2) void pos_kernel(const float* __restrict__ rel)
{
    extern __shared__ float buf[];
    float* Rs0 = buf;
    float* Rs1 = buf + POS_CH*RSTR;
    float* Qs  = buf + 2*POS_CH*RSTR;

    const int t   = blockIdx.x;
    const int tid = threadIdx.x;

    for (int i = tid; i < 64*16; i += 256) {
        int bh = i >> 4;
        int d4 = (i & 15) << 2;
        *(float4*)&Qs[bh*QSTR + d4] =
            *(const float4*)&g_Q[((size_t)bh*TT + t)*DHEAD + d4];
    }

    const int sg = tid & 15;
    const int bg = (tid >> 4) & 1;
    const int h  = tid >> 5;
    const float* relt = rel + (size_t)t*TT*DM;

    pos_load_chunk(relt, 0, Rs0, tid);
    asm volatile("cp.async.commit_group;\n" ::: "memory");

    const int NCH = TT / POS_CH;   // 32
    for (int c = 0; c < NCH; c++) {
        float* cur = (c & 1) ? Rs1 : Rs0;
        float* nxt = (c & 1) ? Rs0 : Rs1;
        if (c + 1 < NCH) {
            pos_load_chunk(relt, (c+1)*POS_CH, nxt, tid);
            asm volatile("cp.async.commit_group;\n" ::: "memory");
            asm volatile("cp.async.wait_group 1;\n" ::: "memory");
        } else {
            asm volatile("cp.async.wait_group 0;\n" ::: "memory");
        }
        __syncthreads();

        uint64_t acc0[4] = {0ull,0ull,0ull,0ull};
#pragma unroll
        for (int d4 = 0; d4 < DHEAD; d4 += 4) {
            ulonglong2 r0 = *(const ulonglong2*)&cur[sg*RSTR + h*QSTR + d4];
#pragma unroll
            for (int i = 0; i < 4; i++) {
                ulonglong2 q = *(const ulonglong2*)&Qs[(((bg<<2)+i)*8 + h)*QSTR + d4];
                ffma2(acc0[i], q.x, r0.x);
                ffma2(acc0[i], q.y, r0.y);
            }
        }
        const int sbase = c*POS_CH;
#pragma unroll
        for (int i = 0; i < 4; i++) {
            int bh = (((bg<<2)+i))*8 + h;
            size_t base = ((size_t)bh*TT + t)*TT + sbase;
            float2 a0 = upk2(acc0[i]);
            float o0 = g_S[base + sg];
            g_S[base + sg] = (o0 + a0.x + a0.y) * 0.125f;
        }
        __syncthreads();
    }

    // ---- fused softmax tail
    const int warp = tid >> 5;
    const int lane = tid & 31;
#pragma unroll
    for (int rr = 0; rr < 8; rr++) {
        int bh = warp*8 + rr;
        float* p = g_S + ((size_t)bh*TT + t)*TT;

        float4 v[4];
        float mx = -1e30f;
#pragma unroll
        for (int i = 0; i < 4; i++) {
            v[i] = *(const float4*)&p[i*128 + lane*4];
            mx = fmaxf(mx, fmaxf(fmaxf(v[i].x, v[i].y), fmaxf(v[i].z, v[i].w)));
        }
#pragma unroll
        for (int o = 16; o > 0; o >>= 1)
            mx = fmaxf(mx, __shfl_xor_sync(0xffffffffu, mx, o));

        float sum = 0.f;
#pragma unroll
        for (int i = 0; i < 4; i++) {
            v[i].x = __expf(v[i].x - mx);
            v[i].y = __expf(v[i].y - mx);
            v[i].z = __expf(v[i].z - mx);
            v[i].w = __expf(v[i].w - mx);
            sum += v[i].x + v[i].y + v[i].z + v[i].w;
        }
#pragma unroll
        for (int o = 16; o > 0; o >>= 1)
            sum += __shfl_xor_sync(0xffffffffu, sum, o);

        const float inv = 1.0f / sum;
#pragma unroll
        for (int i = 0; i < 4; i++) {
            v[i].x *= inv; v[i].y *= inv; v[i].z *= inv; v[i].w *= inv;
            *(float4*)&p[i*128 + lane*4] = v[i];
        }
    }
}

// ---------------- context: C[b,t,h*64+d] = attn[bh] @ V[bh]  (FFMA2 + prefetch) ----
__global__ __launch_bounds__(256,2) void context_kernel()
{
    const int bh = blockIdx.z;
    const int b = bh >> 3, h = bh & 7;
    const float* A  = g_S + (size_t)bh*TT*TT + (size_t)blockIdx.y*128*TT;
    const float* Vp = g_V + (size_t)bh*TT*DHEAD;

    __shared__ float As[32][132];
    __shared__ float Vs[32][68];
    const int tid = threadIdx.x;
    const int ty = tid >> 4, tx = tid & 15;
    uint64_t acc[8][2] = {};

    float4 a_reg[4], v_reg[2];
#pragma unroll
    for (int r = 0; r < 4; r++) {
        int f = tid + (r << 8);
        int row = f >> 3;
        int quad = (f & 7) << 2;
        a_reg[r] = *(const float4*)(A + (size_t)row*TT + quad);
    }
#pragma unroll
    for (int r = 0; r < 2; r++) {
        int f = tid + (r << 8);
        int row = f >> 4;
        int col = (f & 15) << 2;
        v_reg[r] = *(const float4*)(Vp + (size_t)row*DHEAD + col);
    }

    for (int k0 = 0; k0 < TT; k0 += 32) {
#pragma unroll
        for (int r = 0; r < 4; r++) {
            int f = tid + (r << 8);
            int row = f >> 3;
            int quad = (f & 7) << 2;
            As[quad+0][row] = a_reg[r].x; As[quad+1][row] = a_reg[r].y;
            As[quad+2][row] = a_reg[r].z; As[quad+3][row] = a_reg[r].w;
        }
#pragma unroll
        for (int r = 0; r < 2; r++) {
            int f = tid + (r << 8);
            int row = f >> 4;
            int col = (f & 15) << 2;
            *(float4*)&Vs[row][col] = v_reg[r];
        }
        __syncthreads();

        float4 a_nxt[4] = {}, v_nxt[2] = {};
        if (k0 + 32 < TT) {
#pragma unroll
            for (int r = 0; r < 4; r++) {
                int f = tid + (r << 8);
                int row = f >> 3;
                int quad = (f & 7) << 2;
                a_nxt[r] = *(const float4*)(A + (size_t)row*TT + k0 + 32 + quad);
            }
#pragma unroll
            for (int r = 0; r < 2; r++) {
                int f = tid + (r << 8);
                int row = f >> 4;
                int col = (f & 15) << 2;
                v_nxt[r] = *(const float4*)(Vp + (size_t)(k0 + 32 + row)*DHEAD + col);
            }
        }

#pragma unroll
        for (int k = 0; k < 32; k++) {
            float a[8];
            *(float4*)&a[0] = *(const float4*)&As[k][ty*8];
            *(float4*)&a[4] = *(const float4*)&As[k][ty*8+4];
            ulonglong2 bp = *(const ulonglong2*)&Vs[k][tx<<2];
            uint64_t b2[2] = { bp.x, bp.y };
#pragma unroll
            for (int i = 0; i < 8; i++) {
                uint64_t a2 = dup2(a[i]);
                ffma2(acc[i][0], a2, b2[0]);
                ffma2(acc[i][1], a2, b2[1]);
            }
        }
        __syncthreads();
#pragma unroll
        for (int r = 0; r < 4; r++) a_reg[r] = a_nxt[r];
#pragma unroll
        for (int r = 0; r < 2; r++) v_reg[r] = v_nxt[r];
    }
#pragma unroll
    for (int i = 0; i < 8; i++) {
        int t = blockIdx.y*128 + ty*8 + i;
        float2 p0 = upk2(acc[i][0]);
        float2 p1 = upk2(acc[i][1]);
        float4 v = { p0.x, p0.y, p1.x, p1.y };
        *(float4*)&g_C[((size_t)b*TT + t)*DM + h*DHEAD + (tx<<2)] = v;
    }
}

// ---------------- output projection: out = C @ Wo^T + bo ----------------
__global__ __launch_bounds__(256,2) void outproj_kernel(
    const float* __restrict__ Wo, const float* __restrict__ bo,
    float* __restrict__ out)
{
    const float* A  = g_C + (size_t)blockIdx.y * 128 * DM;
    const float* Bm = Wo  + (size_t)blockIdx.x * 128 * DM;
    float acc[4][4][4] = {};
    gemm_abt_tf32(A, Bm, DM, DM, DM, acc);

    const int tid = threadIdx.x;
    const int lane = tid & 31;
    const int wid = tid >> 5;
    const int m0 = (wid >> 2) * 64;
    const int n0 = (wid & 3) * 32;
    const int r4 = lane & 3, q8 = lane >> 2;
#pragma unroll
    for (int mt = 0; mt < 4; mt++) {
#pragma unroll
        for (int nt = 0; nt < 4; nt++) {
            int n = blockIdx.x*128 + n0 + nt*8 + 2*r4;
            float2 bias2 = *(const float2*)&bo[n];
#pragma unroll
            for (int hf = 0; hf < 2; hf++) {
                int m = blockIdx.y*128 + m0 + mt*16 + q8 + hf*8;
                float2 v = { acc[mt][nt][hf*2+0] + bias2.x,
                             acc[mt][nt][hf*2+1] + bias2.y };
                *(float2*)&out[(size_t)m*DM + n] = v;
            }
        }
    }
}

extern "C" void kernel_launch(void* const* d_in, const int* in_sizes, int n_in,
                              void* d_out, int out_size)
{
    const float* x   = (const float*)d_in[0];
    const float* rel = (const float*)d_in[1];
    const float* Wq  = (const float*)d_in[2];
    const float* bq  = (const float*)d_in[3];
    const float* Wk  = (const float*)d_in[4];
    const float* bk  = (const float*)d_in[5];
    const float* Wv  = (const float*)d_in[6];
    const float* bv  = (const float*)d_in[7];
    const float* Wo  = (const float*)d_in[8];
    const float* bo  = (const float*)d_in[9];
    float* out = (float*)d_out;

    cudaFuncSetAttribute(pos_kernel, cudaFuncAttributeMaxDynamicSharedMemorySize, POS_SMEM);

    proj_qkv_kernel<<<dim3(4, 32, 3), 256>>>(x, Wq, bq, Wk, bk, Wv, bv);
    content_kernel<<<dim3(4, 4, 64), 256>>>();
    pos_kernel<<<512, 256, POS_SMEM>>>(rel);
    context_kernel<<<dim3(1, 4, 64), 256>>>();
    outproj_kernel<<<dim3(4, 32), 256>>>(Wo, bo, out);
}